// round 11
// baseline (speedup 1.0000x reference)
#include <cuda_runtime.h>
#include <cuda_fp16.h>
#include <math.h>
#include <stdint.h>

// ContrastiveLoss: loss = sum_i [ logsumexp_j(X_i.Y_j/T) - X_i.Y_i/T ]
// N=8192, C=512, T=0.07. fp16 mma.sync m16n8k16 (fp32 accum), fragment-major
// prepacked operands, warp-specialized producer (cp.async.bulk + mbarrier ring,
// no __syncthreads in mainloop), persistent grid=296 / occ 2, fused LSE.

#define NTOT 8192
#define CDIM 512
#define NCTA 296
#define NUNITS 4096                   // 64 rowblks x 64 coltiles (128x128 tiles)
#define NCOLT 64
#define NPART (NCOLT * 2)

#define STEPS_PER_UNIT 8              // chunk = 64-wide k
#define XSTAGE_BYTES 16384
#define STAGE_BYTES  32768
#define NSTAGE 3
#define MBAR_BYTES 64                 // full[3], empty[3] mbarriers + pad
#define SMEM_TOTAL (MBAR_BYTES + NSTAGE * STAGE_BYTES)   // 98368 -> occ 2

#define PLANE_HALFS 524288

#define SCALE_LOG2 (14.285714285714286f * 1.4426950408889634f)
#define LN2 0.6931471805599453f

// -------- scratch --------
__device__ __align__(16) __half g_Xh[NTOT * CDIM];
__device__ __align__(16) __half g_Yh[NTOT * CDIM];
__device__ float g_m[NPART][NTOT];
__device__ float g_l[NPART][NTOT];
__device__ float g_pos[NTOT];
__device__ float g_bsum[32];
__device__ unsigned int g_done;

__device__ __forceinline__ float ex2f(float x) {
    float y; asm("ex2.approx.ftz.f32 %0, %1;" : "=f"(y) : "f"(x)); return y;
}
__device__ __forceinline__ uint32_t smem_to_u32(const void* p) {
    uint32_t a;
    asm("{ .reg .u64 t; cvta.to.shared.u64 t, %1; cvt.u32.u64 %0, t; }" : "=r"(a) : "l"(p));
    return a;
}
__device__ __forceinline__ uint32_t pk(float a, float b) {
    __half2 h = __floats2half2_rn(a, b);
    return *reinterpret_cast<uint32_t*>(&h);
}
__device__ __forceinline__ void mma_f16(float* c, const uint4 a, uint32_t b0, uint32_t b1) {
    asm volatile(
        "mma.sync.aligned.m16n8k16.row.col.f32.f16.f16.f32 "
        "{%0,%1,%2,%3}, {%4,%5,%6,%7}, {%8,%9}, {%0,%1,%2,%3};"
        : "+f"(c[0]), "+f"(c[1]), "+f"(c[2]), "+f"(c[3])
        : "r"(a.x), "r"(a.y), "r"(a.z), "r"(a.w), "r"(b0), "r"(b1));
}

#define MBARRIER_INIT(mbar, count) \
    asm volatile("mbarrier.init.shared.b64 [%0], %1;" :: "r"((uint32_t)(mbar)), "r"((uint32_t)(count)) : "memory")
#define MBARRIER_EXPECT_TX(mbar, bytes) \
    asm volatile("mbarrier.arrive.expect_tx.shared.b64 _, [%0], %1;" :: "r"((uint32_t)(mbar)), "r"((uint32_t)(bytes)) : "memory")
#define MBARRIER_ARRIVE(mbar) \
    asm volatile("mbarrier.arrive.shared.b64 _, [%0];" :: "r"((uint32_t)(mbar)) : "memory")

#define MBARRIER_WAIT_ACQ(mbar, ph) do { \
    uint32_t _m = (uint32_t)(mbar); uint32_t _p = (uint32_t)(ph); uint32_t _d; \
    asm volatile("{\n\t.reg .pred p;\n\t" \
        "mbarrier.try_wait.parity.acquire.cta.shared::cta.b64 p, [%1], %2;\n\t" \
        "selp.b32 %0, 1, 0, p;\n\t}" : "=r"(_d) : "r"(_m), "r"(_p) : "memory"); \
    if (!_d) { asm volatile("{\n\t.reg .pred P1;\n\t" \
        "WL_%=:\n\tmbarrier.try_wait.parity.acquire.cta.shared::cta.b64 P1, [%0], %1, 0x989680;\n\t" \
        "@P1 bra.uni WD_%=;\n\tbra.uni WL_%=;\n\tWD_%=:\n\t}" :: "r"(_m), "r"(_p) : "memory"); } \
} while (0)

#define MBARRIER_WAIT_RLX(mbar, ph) do { \
    uint32_t _m = (uint32_t)(mbar); uint32_t _p = (uint32_t)(ph); uint32_t _d; \
    asm volatile("{\n\t.reg .pred p;\n\t" \
        "mbarrier.try_wait.parity.relaxed.cta.shared::cta.b64 p, [%1], %2, 0x989680;\n\t" \
        "selp.b32 %0, 1, 0, p;\n\t}" : "=r"(_d) : "r"(_m), "r"(_p) : "memory"); \
    if (!_d) { asm volatile("{\n\t.reg .pred P1;\n\t" \
        "WL_%=:\n\tmbarrier.try_wait.parity.relaxed.cta.shared::cta.b64 P1, [%0], %1, 0x989680;\n\t" \
        "@P1 bra.uni WD_%=;\n\tbra.uni WL_%=;\n\tWD_%=:\n\t}" :: "r"(_m), "r"(_p) : "memory"); } \
} while (0)

__device__ __forceinline__ void bulk_copy(uint32_t dst, const void* src, uint32_t bytes, uint32_t mbar) {
    asm volatile("cp.async.bulk.shared::cluster.global.mbarrier::complete_tx::bytes [%0], [%1], %2, [%3];"
                 :: "r"(dst), "l"(src), "r"(bytes), "r"(mbar) : "memory");
}

// -------- pre-kernel: fp16 round + fragment-major packing (as R10) --------
__global__ void __launch_bounds__(256)
cl_pre_kernel(const float* __restrict__ X, const float* __restrict__ Y) {
    const uint32_t gid = blockIdx.x * 256u + threadIdx.x;
    const uint32_t NFRAG = 524288;
    if (gid < NFRAG) {
        const uint32_t fid = gid;
        const uint32_t lane = fid & 31, k16 = (fid >> 5) & 3, rb = (fid >> 7) & 511, kc = fid >> 16;
        const uint32_t g = lane >> 2, q = lane & 3;
        const uint32_t k0 = kc * 64 + k16 * 16;
        const float* r0 = X + (size_t)(rb * 16 + g) * CDIM + k0;
        const float* r1 = r0 + 8 * CDIM;
        uint4 o;
        o.x = pk(r0[2 * q], r0[2 * q + 1]);
        o.y = pk(r1[2 * q], r1[2 * q + 1]);
        o.z = pk(r0[2 * q + 8], r0[2 * q + 9]);
        o.w = pk(r1[2 * q + 8], r1[2 * q + 9]);
        *reinterpret_cast<uint4*>(reinterpret_cast<char*>(g_Xh) + (size_t)fid * 16) = o;
    } else {
        const uint32_t fid = gid - NFRAG;
        const uint32_t lane = fid & 31, kp = (fid >> 5) & 1, cb = (fid >> 6) & 1023, kc = fid >> 16;
        const uint32_t g = lane >> 2, q = lane & 3;
        const uint32_t k0 = kc * 64 + kp * 32;
        const float* r = Y + (size_t)(cb * 8 + g) * CDIM + k0;
        uint4 o;
        o.x = pk(r[2 * q], r[2 * q + 1]);
        o.y = pk(r[2 * q + 8], r[2 * q + 9]);
        o.z = pk(r[16 + 2 * q], r[16 + 2 * q + 1]);
        o.w = pk(r[16 + 2 * q + 8], r[16 + 2 * q + 9]);
        *reinterpret_cast<uint4*>(reinterpret_cast<char*>(g_Yh) + (size_t)fid * 16) = o;
    }
}

// -------- main kernel: 4 compute warps + 1 producer warp, mbarrier ring --------
__global__ void __launch_bounds__(160, 2)
cl_mma_kernel() {
    extern __shared__ __align__(16) char smem[];
    const uint32_t sb = smem_to_u32(smem);
    const uint4* sm4 = reinterpret_cast<const uint4*>(smem + MBAR_BYTES);

    const int tid = threadIdx.x;
    const int wid = tid >> 5;
    const int lane = tid & 31;

    const int b = blockIdx.x;
    const int njobs = (NUNITS - 1 - b) / NCTA + 1;   // 13 or 14
    const int nsteps = njobs * STEPS_PER_UNIT;

    const uint32_t mb_full = sb;           // 3 x 8 bytes
    const uint32_t mb_empty = sb + 24;     // 3 x 8 bytes
    const uint32_t data = sb + MBAR_BYTES;

    if (tid == 0) {
        for (int s = 0; s < NSTAGE; s++) {
            MBARRIER_INIT(mb_full + s * 8, 1);    // expect_tx arrive
            MBARRIER_INIT(mb_empty + s * 8, 4);   // 4 compute warps
        }
    }
    __syncthreads();

    if (wid == 4) {
        // ---------------- producer warp (single thread) ----------------
        if (lane == 0) {
            for (int s = 0; s < nsteps; s++) {
                const int st = s % NSTAGE;
                const int lap = s / NSTAGE;
                if (lap > 0) MBARRIER_WAIT_RLX(mb_empty + st * 8, (lap - 1) & 1);
                const int j = s >> 3;
                const int kc = s & 7;
                const int uid = b + NCTA * j;
                const int row0 = (uid >> 6) * 128;
                const int col0 = (uid & 63) * 128;
                const __half* xsrc = g_Xh + (size_t)kc * PLANE_HALFS + (size_t)(row0 >> 4) * 1024;
                const __half* ysrc = g_Yh + (size_t)kc * PLANE_HALFS + (size_t)(col0 >> 3) * 512;
                MBARRIER_EXPECT_TX(mb_full + st * 8, STAGE_BYTES);
                bulk_copy(data + st * STAGE_BYTES, xsrc, XSTAGE_BYTES, mb_full + st * 8);
                bulk_copy(data + st * STAGE_BYTES + XSTAGE_BYTES, ysrc, XSTAGE_BYTES, mb_full + st * 8);
            }
        }
        return;
    }

    // ---------------- compute warps 0..3 ----------------
    const int g = lane >> 2;
    const int q = lane & 3;
    const int warpM = wid >> 1;       // 0..1
    const int warpN = wid & 1;        // 0..1

    float acc[4][8][4];
#pragma unroll
    for (int mb = 0; mb < 4; mb++)
#pragma unroll
        for (int nb = 0; nb < 8; nb++)
#pragma unroll
            for (int c = 0; c < 4; c++) acc[mb][nb][c] = 0.0f;

    for (int s = 0; s < nsteps; s++) {
        const int st = s % NSTAGE;
        const int lap = s / NSTAGE;
        MBARRIER_WAIT_ACQ(mb_full + st * 8, lap & 1);

        const uint4* Xf = sm4 + (st * STAGE_BYTES) / 16;   // [rb(8)][k16(4)][lane]
        const uint4* Yf = Xf + XSTAGE_BYTES / 16;          // [cb(16)][kpair(2)][lane]

#pragma unroll
        for (int kp = 0; kp < 2; kp++) {
            uint4 bq[8];
#pragma unroll
            for (int nb = 0; nb < 8; nb++)
                bq[nb] = Yf[((warpN * 8 + nb) * 2 + kp) * 32 + lane];
#pragma unroll
            for (int half = 0; half < 2; half++) {
                const int k16 = kp * 2 + half;
#pragma unroll
                for (int mb = 0; mb < 4; mb++) {
                    const uint4 av = Xf[((warpM * 4 + mb) * 4 + k16) * 32 + lane];
#pragma unroll
                    for (int nb = 0; nb < 8; nb++) {
                        if (half == 0) mma_f16(acc[mb][nb], av, bq[nb].x, bq[nb].y);
                        else           mma_f16(acc[mb][nb], av, bq[nb].z, bq[nb].w);
                    }
                }
            }
        }

        __syncwarp();
        if (lane == 0) MBARRIER_ARRIVE(mb_empty + st * 8);

        // per-unit epilogue (registers only; overlaps other warps' MMA)
        if ((s & 7) == 7) {
            const int uid = b + NCTA * (s >> 3);
            const int row0 = (uid >> 6) * 128;
            const int ct = uid & 63;
            const int sp = ct * 2 + warpN;
            const int col0 = ct * 128 + warpN * 64;
#pragma unroll
            for (int mb = 0; mb < 4; mb++) {
#pragma unroll
                for (int pr = 0; pr < 2; pr++) {
                    const int grow = row0 + warpM * 64 + mb * 16 + pr * 8 + g;
                    float v[16];
                    float tmax = -INFINITY;
#pragma unroll
                    for (int nb = 0; nb < 8; nb++) {
                        v[2 * nb] = acc[mb][nb][2 * pr] * SCALE_LOG2;
                        v[2 * nb + 1] = acc[mb][nb][2 * pr + 1] * SCALE_LOG2;
                        tmax = fmaxf(tmax, fmaxf(v[2 * nb], v[2 * nb + 1]));
                    }
                    tmax = fmaxf(tmax, __shfl_xor_sync(0xffffffffu, tmax, 1));
                    tmax = fmaxf(tmax, __shfl_xor_sync(0xffffffffu, tmax, 2));
                    float sum = 0.0f;
#pragma unroll
                    for (int nb = 0; nb < 8; nb++) {
                        const int gc = col0 + nb * 8 + q * 2;
                        sum += ex2f(v[2 * nb] - tmax) + ex2f(v[2 * nb + 1] - tmax);
                        if (gc == grow) g_pos[grow] = v[2 * nb];
                        if (gc + 1 == grow) g_pos[grow] = v[2 * nb + 1];
                    }
                    sum += __shfl_xor_sync(0xffffffffu, sum, 1);
                    sum += __shfl_xor_sync(0xffffffffu, sum, 2);
                    if (q == 0) {
                        g_m[sp][grow] = tmax;
                        g_l[sp][grow] = sum;
                    }
                }
            }
#pragma unroll
            for (int mb = 0; mb < 4; mb++)
#pragma unroll
                for (int nb = 0; nb < 8; nb++)
#pragma unroll
                    for (int c = 0; c < 4; c++) acc[mb][nb][c] = 0.0f;
        }
    }
}

// -------- fused combine + reduce (grid 32; last block finishes) --------
__global__ void cl_combine_kernel(float* __restrict__ out) {
    __shared__ float sh[256];
    const int i = blockIdx.x * 256 + threadIdx.x;
    float M = -INFINITY;
#pragma unroll 8
    for (int s = 0; s < NPART; s++) M = fmaxf(M, g_m[s][i]);
    float L = 0.0f;
#pragma unroll 8
    for (int s = 0; s < NPART; s++) L += g_l[s][i] * ex2f(g_m[s][i] - M);
    sh[threadIdx.x] = M + __log2f(L) - g_pos[i];
    __syncthreads();
    for (int o = 128; o > 0; o >>= 1) {
        if (threadIdx.x < o) sh[threadIdx.x] += sh[threadIdx.x + o];
        __syncthreads();
    }
    if (threadIdx.x == 0) {
        g_bsum[blockIdx.x] = sh[0];
        __threadfence();
        const unsigned int t = atomicAdd(&g_done, 1u);
        if (t == 31u) {
            float tot = 0.0f;
#pragma unroll
            for (int k = 0; k < 32; k++) tot += g_bsum[k];
            out[0] = tot * LN2;
            g_done = 0u;   // reset for graph replay
        }
    }
}

extern "C" void kernel_launch(void* const* d_in, const int* in_sizes, int n_in,
                              void* d_out, int out_size) {
    const float* X = (const float*)d_in[0];
    const float* Y = (const float*)d_in[1];
    float* out = (float*)d_out;

    cudaFuncSetAttribute(cl_mma_kernel, cudaFuncAttributeMaxDynamicSharedMemorySize, SMEM_TOTAL);

    cl_pre_kernel<<<4096, 256>>>(X, Y);
    cl_mma_kernel<<<NCTA, 160, SMEM_TOTAL>>>();
    cl_combine_kernel<<<32, 256>>>(out);
}

// round 12
// speedup vs baseline: 1.8445x; 1.8445x over previous
#include <cuda_runtime.h>
#include <cuda_fp16.h>
#include <math.h>
#include <stdint.h>

// ContrastiveLoss: loss = sum_i [ logsumexp_j(X_i.Y_j/T) - X_i.Y_i/T ]
// N=8192, C=512, T=0.07. fp16 mma.sync m16n8k16 (fp32 accum), fragment-major
// prepacked operands, 4-warp CTAs / 64x64 warp tiles / occ 2, persistent
// grid=296 static schedule, 3-stage cp.async ring with mid-compute issue,
// fused per-stripe logsumexp partials + single-pass combine/reduce.

#define NTOT 8192
#define CDIM 512
#define NCTA 296
#define NUNITS 4096                   // 64 rowblks x 64 coltiles (128x128 tiles)
#define NCOLT 64
#define NPART (NCOLT * 2)

#define STEPS_PER_UNIT 8              // step = 64-wide k chunk
#define XSTAGE_BYTES 16384
#define STAGE_BYTES  32768
#define NSTAGE 3
#define SMEM_TOTAL (NSTAGE * STAGE_BYTES)   // 98304 -> occ 2

#define PLANE_HALFS 524288

#define SCALE_LOG2 (14.285714285714286f * 1.4426950408889634f)
#define LN2 0.6931471805599453f

// -------- scratch (device globals; no allocation allowed) --------
__device__ __align__(16) __half g_Xh[NTOT * CDIM];
__device__ __align__(16) __half g_Yh[NTOT * CDIM];
__device__ float g_m[NPART][NTOT];
__device__ float g_l[NPART][NTOT];
__device__ float g_pos[NTOT];
__device__ float g_bsum[32];
__device__ unsigned int g_done;

__device__ __forceinline__ float ex2f(float x) {
    float y; asm("ex2.approx.ftz.f32 %0, %1;" : "=f"(y) : "f"(x)); return y;
}
__device__ __forceinline__ uint32_t smem_to_u32(const void* p) {
    uint32_t a;
    asm("{ .reg .u64 t; cvta.to.shared.u64 t, %1; cvt.u32.u64 %0, t; }" : "=r"(a) : "l"(p));
    return a;
}
__device__ __forceinline__ void cp_async16(uint32_t dst, const void* src) {
    asm volatile("cp.async.ca.shared.global [%0], [%1], 16;" :: "r"(dst), "l"(src) : "memory");
}
#define CP_COMMIT() asm volatile("cp.async.commit_group;" ::: "memory")
#define CP_WAIT_1() asm volatile("cp.async.wait_group 1;" ::: "memory")

__device__ __forceinline__ uint32_t pk(float a, float b) {
    __half2 h = __floats2half2_rn(a, b);
    return *reinterpret_cast<uint32_t*>(&h);
}
__device__ __forceinline__ void mma_f16(float* c, const uint4 a, uint32_t b0, uint32_t b1) {
    asm volatile(
        "mma.sync.aligned.m16n8k16.row.col.f32.f16.f16.f32 "
        "{%0,%1,%2,%3}, {%4,%5,%6,%7}, {%8,%9}, {%0,%1,%2,%3};"
        : "+f"(c[0]), "+f"(c[1]), "+f"(c[2]), "+f"(c[3])
        : "r"(a.x), "r"(a.y), "r"(a.z), "r"(a.w), "r"(b0), "r"(b1));
}

// -------- pre-kernel: fp16 round + fragment-major packing (as R10) --------
__global__ void __launch_bounds__(256)
cl_pre_kernel(const float* __restrict__ X, const float* __restrict__ Y) {
    const uint32_t gid = blockIdx.x * 256u + threadIdx.x;
    const uint32_t NFRAG = 524288;
    if (gid < NFRAG) {
        const uint32_t fid = gid;
        const uint32_t lane = fid & 31, k16 = (fid >> 5) & 3, rb = (fid >> 7) & 511, kc = fid >> 16;
        const uint32_t g = lane >> 2, q = lane & 3;
        const uint32_t k0 = kc * 64 + k16 * 16;
        const float* r0 = X + (size_t)(rb * 16 + g) * CDIM + k0;
        const float* r1 = r0 + 8 * CDIM;
        uint4 o;
        o.x = pk(r0[2 * q], r0[2 * q + 1]);
        o.y = pk(r1[2 * q], r1[2 * q + 1]);
        o.z = pk(r0[2 * q + 8], r0[2 * q + 9]);
        o.w = pk(r1[2 * q + 8], r1[2 * q + 9]);
        *reinterpret_cast<uint4*>(reinterpret_cast<char*>(g_Xh) + (size_t)fid * 16) = o;
    } else {
        const uint32_t fid = gid - NFRAG;
        const uint32_t lane = fid & 31, kp = (fid >> 5) & 1, cb = (fid >> 6) & 1023, kc = fid >> 16;
        const uint32_t g = lane >> 2, q = lane & 3;
        const uint32_t k0 = kc * 64 + kp * 32;
        const float* r = Y + (size_t)(cb * 8 + g) * CDIM + k0;
        uint4 o;
        o.x = pk(r[2 * q], r[2 * q + 1]);
        o.y = pk(r[2 * q + 8], r[2 * q + 9]);
        o.z = pk(r[16 + 2 * q], r[16 + 2 * q + 1]);
        o.w = pk(r[16 + 2 * q + 8], r[16 + 2 * q + 9]);
        *reinterpret_cast<uint4*>(reinterpret_cast<char*>(g_Yh) + (size_t)fid * 16) = o;
    }
}

// -------- main kernel: persistent, 4 warps, 64x64 warp tiles, fp16 --------
__global__ void __launch_bounds__(128, 2)
cl_mma_kernel() {
    extern __shared__ __align__(16) char smem[];
    const uint32_t sb = smem_to_u32(smem);
    const uint4* sm4 = reinterpret_cast<const uint4*>(smem);

    const int tid = threadIdx.x;
    const int wid = tid >> 5;
    const int lane = tid & 31;
    const int g = lane >> 2;
    const int q = lane & 3;
    const int warpM = wid >> 1;
    const int warpN = wid & 1;

    const int b = blockIdx.x;
    const int njobs = (NUNITS - 1 - b) / NCTA + 1;   // 13 or 14
    const int nsteps = njobs * STEPS_PER_UNIT;

    auto load_stage = [&](int s, int buf) {
        if (s < nsteps) {
            const int j = s >> 3;
            const int kc = s & 7;
            const int uid = b + NCTA * j;
            const int row0 = (uid >> 6) * 128;
            const int col0 = (uid & 63) * 128;
            const __half* xsrc = g_Xh + (size_t)kc * PLANE_HALFS + (size_t)(row0 >> 4) * 1024;
            const __half* ysrc = g_Yh + (size_t)kc * PLANE_HALFS + (size_t)(col0 >> 3) * 512;
            const uint32_t xd = sb + buf * STAGE_BYTES;
            const uint32_t yd = xd + XSTAGE_BYTES;
#pragma unroll
            for (int i = 0; i < 8; i++) {
                const int c = tid + i * 128;
                cp_async16(xd + c * 16, xsrc + c * 8);
                cp_async16(yd + c * 16, ysrc + c * 8);
            }
        }
        CP_COMMIT();
    };

    float acc[4][8][4];
#pragma unroll
    for (int mb = 0; mb < 4; mb++)
#pragma unroll
        for (int nb = 0; nb < 8; nb++)
#pragma unroll
            for (int c = 0; c < 4; c++) acc[mb][nb][c] = 0.0f;

    load_stage(0, 0);
    load_stage(1, 1);

    for (int s = 0; s < nsteps; s++) {
        const int buf = s % NSTAGE;

        // sync (protects buffer (s+2)%3 reuse) -> ensure stage s resident
        __syncthreads();
        CP_WAIT_1();

        const uint4* Xf = sm4 + (buf * STAGE_BYTES) / 16;   // [rb(8)][k16(4)][lane]
        const uint4* Yf = Xf + XSTAGE_BYTES / 16;           // [cb(16)][kpair(2)][lane]

#pragma unroll
        for (int kp = 0; kp < 2; kp++) {
            uint4 bq[8];
#pragma unroll
            for (int nb = 0; nb < 8; nb++)
                bq[nb] = Yf[((warpN * 8 + nb) * 2 + kp) * 32 + lane];
#pragma unroll
            for (int half = 0; half < 2; half++) {
                const int k16 = kp * 2 + half;
#pragma unroll
                for (int mb = 0; mb < 4; mb++) {
                    const uint4 av = Xf[((warpM * 4 + mb) * 4 + k16) * 32 + lane];
#pragma unroll
                    for (int nb = 0; nb < 8; nb++) {
                        if (half == 0) mma_f16(acc[mb][nb], av, bq[nb].x, bq[nb].y);
                        else           mma_f16(acc[mb][nb], av, bq[nb].z, bq[nb].w);
                    }
                }
            }
            // mid-compute prefetch issue: LSU burst overlaps second compute half
            if (kp == 0) load_stage(s + 2, (s + 2) % NSTAGE);
        }

        // per-unit epilogue: stripe-local (max, sum) partials, then reset acc
        if ((s & 7) == 7) {
            const int uid = b + NCTA * (s >> 3);
            const int row0 = (uid >> 6) * 128;
            const int ct = uid & 63;
            const int sp = ct * 2 + warpN;
            const int col0 = ct * 128 + warpN * 64;
#pragma unroll
            for (int mb = 0; mb < 4; mb++) {
#pragma unroll
                for (int pr = 0; pr < 2; pr++) {
                    const int grow = row0 + warpM * 64 + mb * 16 + pr * 8 + g;
                    float v[16];
                    float tmax = -INFINITY;
#pragma unroll
                    for (int nb = 0; nb < 8; nb++) {
                        v[2 * nb] = acc[mb][nb][2 * pr] * SCALE_LOG2;
                        v[2 * nb + 1] = acc[mb][nb][2 * pr + 1] * SCALE_LOG2;
                        tmax = fmaxf(tmax, fmaxf(v[2 * nb], v[2 * nb + 1]));
                    }
                    tmax = fmaxf(tmax, __shfl_xor_sync(0xffffffffu, tmax, 1));
                    tmax = fmaxf(tmax, __shfl_xor_sync(0xffffffffu, tmax, 2));
                    float sum = 0.0f;
#pragma unroll
                    for (int nb = 0; nb < 8; nb++) {
                        const int gc = col0 + nb * 8 + q * 2;
                        sum += ex2f(v[2 * nb] - tmax) + ex2f(v[2 * nb + 1] - tmax);
                        if (gc == grow) g_pos[grow] = v[2 * nb];
                        if (gc + 1 == grow) g_pos[grow] = v[2 * nb + 1];
                    }
                    sum += __shfl_xor_sync(0xffffffffu, sum, 1);
                    sum += __shfl_xor_sync(0xffffffffu, sum, 2);
                    if (q == 0) {
                        g_m[sp][grow] = tmax;
                        g_l[sp][grow] = sum;
                    }
                }
            }
#pragma unroll
            for (int mb = 0; mb < 4; mb++)
#pragma unroll
                for (int nb = 0; nb < 8; nb++)
#pragma unroll
                    for (int c = 0; c < 4; c++) acc[mb][nb][c] = 0.0f;
        }
    }
}

// -------- fused combine + reduce (grid 32; last block finishes) --------
__global__ void cl_combine_kernel(float* __restrict__ out) {
    __shared__ float sh[256];
    const int i = blockIdx.x * 256 + threadIdx.x;
    float M = -INFINITY;
#pragma unroll 8
    for (int s = 0; s < NPART; s++) M = fmaxf(M, g_m[s][i]);
    float L = 0.0f;
#pragma unroll 8
    for (int s = 0; s < NPART; s++) L += g_l[s][i] * ex2f(g_m[s][i] - M);
    sh[threadIdx.x] = M + __log2f(L) - g_pos[i];
    __syncthreads();
    for (int o = 128; o > 0; o >>= 1) {
        if (threadIdx.x < o) sh[threadIdx.x] += sh[threadIdx.x + o];
        __syncthreads();
    }
    if (threadIdx.x == 0) {
        g_bsum[blockIdx.x] = sh[0];
        __threadfence();
        const unsigned int t = atomicAdd(&g_done, 1u);
        if (t == 31u) {
            float tot = 0.0f;
#pragma unroll
            for (int k = 0; k < 32; k++) tot += g_bsum[k];
            out[0] = tot * LN2;
            g_done = 0u;   // reset for graph replay
        }
    }
}

extern "C" void kernel_launch(void* const* d_in, const int* in_sizes, int n_in,
                              void* d_out, int out_size) {
    const float* X = (const float*)d_in[0];
    const float* Y = (const float*)d_in[1];
    float* out = (float*)d_out;

    cudaFuncSetAttribute(cl_mma_kernel, cudaFuncAttributeMaxDynamicSharedMemorySize, SMEM_TOTAL);

    cl_pre_kernel<<<4096, 256>>>(X, Y);
    cl_mma_kernel<<<NCTA, 128, SMEM_TOTAL>>>();
    cl_combine_kernel<<<32, 256>>>(out);
}

// round 14
// speedup vs baseline: 1.8481x; 1.0019x over previous
#include <cuda_runtime.h>
#include <cuda_fp16.h>
#include <math.h>
#include <stdint.h>

// ContrastiveLoss: loss = sum_i [ logsumexp_j(X_i.Y_j/T) - X_i.Y_i/T ]
// N=8192, C=512, T=0.07. fp16 mma.sync m16n8k16 (fp32 accum), fragment-major
// prepacked operands, 4-warp CTAs / 64x64 warp tiles / occ 2, persistent
// grid=296 static schedule, 3-stage cp.async ring with mid-compute issue and
// RACE-FREE wait->barrier->read ordering, fused LSE partials + 1-pass reduce.

#define NTOT 8192
#define CDIM 512
#define NCTA 296
#define NUNITS 4096                   // 64 rowblks x 64 coltiles (128x128 tiles)
#define NCOLT 64
#define NPART (NCOLT * 2)

#define STEPS_PER_UNIT 8              // step = 64-wide k chunk
#define XSTAGE_BYTES 16384
#define STAGE_BYTES  32768
#define NSTAGE 3
#define SMEM_TOTAL (NSTAGE * STAGE_BYTES)   // 98304 -> occ 2

#define PLANE_HALFS 524288

#define SCALE_LOG2 (14.285714285714286f * 1.4426950408889634f)
#define LN2 0.6931471805599453f

// -------- scratch (device globals; no allocation allowed) --------
__device__ __align__(16) __half g_Xh[NTOT * CDIM];
__device__ __align__(16) __half g_Yh[NTOT * CDIM];
__device__ float g_m[NPART][NTOT];
__device__ float g_l[NPART][NTOT];
__device__ float g_pos[NTOT];
__device__ float g_bsum[32];
__device__ unsigned int g_done;

__device__ __forceinline__ float ex2f(float x) {
    float y; asm("ex2.approx.ftz.f32 %0, %1;" : "=f"(y) : "f"(x)); return y;
}
__device__ __forceinline__ uint32_t smem_to_u32(const void* p) {
    uint32_t a;
    asm("{ .reg .u64 t; cvta.to.shared.u64 t, %1; cvt.u32.u64 %0, t; }" : "=r"(a) : "l"(p));
    return a;
}
__device__ __forceinline__ void cp_async16(uint32_t dst, const void* src) {
    asm volatile("cp.async.ca.shared.global [%0], [%1], 16;" :: "r"(dst), "l"(src) : "memory");
}
#define CP_COMMIT() asm volatile("cp.async.commit_group;" ::: "memory")
#define CP_WAIT_1() asm volatile("cp.async.wait_group 1;" ::: "memory")

__device__ __forceinline__ uint32_t pk(float a, float b) {
    __half2 h = __floats2half2_rn(a, b);
    return *reinterpret_cast<uint32_t*>(&h);
}
__device__ __forceinline__ void mma_f16(float* c, const uint4 a, uint32_t b0, uint32_t b1) {
    asm volatile(
        "mma.sync.aligned.m16n8k16.row.col.f32.f16.f16.f32 "
        "{%0,%1,%2,%3}, {%4,%5,%6,%7}, {%8,%9}, {%0,%1,%2,%3};"
        : "+f"(c[0]), "+f"(c[1]), "+f"(c[2]), "+f"(c[3])
        : "r"(a.x), "r"(a.y), "r"(a.z), "r"(a.w), "r"(b0), "r"(b1));
}

// -------- pre-kernel: fp16 round + fragment-major packing --------
__global__ void __launch_bounds__(256)
cl_pre_kernel(const float* __restrict__ X, const float* __restrict__ Y) {
    const uint32_t gid = blockIdx.x * 256u + threadIdx.x;
    const uint32_t NFRAG = 524288;
    if (gid < NFRAG) {
        const uint32_t fid = gid;
        const uint32_t lane = fid & 31, k16 = (fid >> 5) & 3, rb = (fid >> 7) & 511, kc = fid >> 16;
        const uint32_t g = lane >> 2, q = lane & 3;
        const uint32_t k0 = kc * 64 + k16 * 16;
        const float* r0 = X + (size_t)(rb * 16 + g) * CDIM + k0;
        const float* r1 = r0 + 8 * CDIM;
        uint4 o;
        o.x = pk(r0[2 * q], r0[2 * q + 1]);
        o.y = pk(r1[2 * q], r1[2 * q + 1]);
        o.z = pk(r0[2 * q + 8], r0[2 * q + 9]);
        o.w = pk(r1[2 * q + 8], r1[2 * q + 9]);
        *reinterpret_cast<uint4*>(reinterpret_cast<char*>(g_Xh) + (size_t)fid * 16) = o;
    } else {
        const uint32_t fid = gid - NFRAG;
        const uint32_t lane = fid & 31, kp = (fid >> 5) & 1, cb = (fid >> 6) & 1023, kc = fid >> 16;
        const uint32_t g = lane >> 2, q = lane & 3;
        const uint32_t k0 = kc * 64 + kp * 32;
        const float* r = Y + (size_t)(cb * 8 + g) * CDIM + k0;
        uint4 o;
        o.x = pk(r[2 * q], r[2 * q + 1]);
        o.y = pk(r[2 * q + 8], r[2 * q + 9]);
        o.z = pk(r[16 + 2 * q], r[16 + 2 * q + 1]);
        o.w = pk(r[16 + 2 * q + 8], r[16 + 2 * q + 9]);
        *reinterpret_cast<uint4*>(reinterpret_cast<char*>(g_Yh) + (size_t)fid * 16) = o;
    }
}

// -------- main kernel: persistent, 4 warps, 64x64 warp tiles, fp16 --------
__global__ void __launch_bounds__(128, 2)
cl_mma_kernel() {
    extern __shared__ __align__(16) char smem[];
    const uint32_t sb = smem_to_u32(smem);
    const uint4* sm4 = reinterpret_cast<const uint4*>(smem);

    const int tid = threadIdx.x;
    const int wid = tid >> 5;
    const int lane = tid & 31;
    const int g = lane >> 2;
    const int q = lane & 3;
    const int warpM = wid >> 1;
    const int warpN = wid & 1;

    const int b = blockIdx.x;
    const int njobs = (NUNITS - 1 - b) / NCTA + 1;   // 13 or 14
    const int nsteps = njobs * STEPS_PER_UNIT;

    auto load_stage = [&](int s, int buf) {
        if (s < nsteps) {
            const int j = s >> 3;
            const int kc = s & 7;
            const int uid = b + NCTA * j;
            const int row0 = (uid >> 6) * 128;
            const int col0 = (uid & 63) * 128;
            const __half* xsrc = g_Xh + (size_t)kc * PLANE_HALFS + (size_t)(row0 >> 4) * 1024;
            const __half* ysrc = g_Yh + (size_t)kc * PLANE_HALFS + (size_t)(col0 >> 3) * 512;
            const uint32_t xd = sb + buf * STAGE_BYTES;
            const uint32_t yd = xd + XSTAGE_BYTES;
#pragma unroll
            for (int i = 0; i < 8; i++) {
                const int c = tid + i * 128;
                cp_async16(xd + c * 16, xsrc + c * 8);
                cp_async16(yd + c * 16, ysrc + c * 8);
            }
        }
        CP_COMMIT();
    };

    float acc[4][8][4];
#pragma unroll
    for (int mb = 0; mb < 4; mb++)
#pragma unroll
        for (int nb = 0; nb < 8; nb++)
#pragma unroll
            for (int c = 0; c < 4; c++) acc[mb][nb][c] = 0.0f;

    load_stage(0, 0);
    load_stage(1, 1);

    for (int s = 0; s < nsteps; s++) {
        const int buf = s % NSTAGE;

        // RACE-FREE ordering: own-wait -> barrier -> read.
        // CP_WAIT_1: pending {g(s), g(s+1)} -> own g(s) complete (issued 2 steps
        // ago, so normally already satisfied; no pipeline drain).
        // __syncthreads: ALL threads' g(s) complete before any smem read of
        // stage s; also orders step s-1's reads of buffer (s-1)%3 before this
        // step's mid-compute issue into (s+2)%3 == (s-1)%3.
        CP_WAIT_1();
        __syncthreads();

        const uint4* Xf = sm4 + (buf * STAGE_BYTES) / 16;   // [rb(8)][k16(4)][lane]
        const uint4* Yf = Xf + XSTAGE_BYTES / 16;           // [cb(16)][kpair(2)][lane]

#pragma unroll
        for (int kp = 0; kp < 2; kp++) {
            uint4 bq[8];
#pragma unroll
            for (int nb = 0; nb < 8; nb++)
                bq[nb] = Yf[((warpN * 8 + nb) * 2 + kp) * 32 + lane];
#pragma unroll
            for (int half = 0; half < 2; half++) {
                const int k16 = kp * 2 + half;
#pragma unroll
                for (int mb = 0; mb < 4; mb++) {
                    const uint4 av = Xf[((warpM * 4 + mb) * 4 + k16) * 32 + lane];
#pragma unroll
                    for (int nb = 0; nb < 8; nb++) {
                        if (half == 0) mma_f16(acc[mb][nb], av, bq[nb].x, bq[nb].y);
                        else           mma_f16(acc[mb][nb], av, bq[nb].z, bq[nb].w);
                    }
                }
            }
            // mid-compute prefetch issue: LSU burst overlaps second compute half
            if (kp == 0) load_stage(s + 2, (s + 2) % NSTAGE);
        }

        // per-unit epilogue: stripe-local (max, sum) partials, then reset acc
        if ((s & 7) == 7) {
            const int uid = b + NCTA * (s >> 3);
            const int row0 = (uid >> 6) * 128;
            const int ct = uid & 63;
            const int sp = ct * 2 + warpN;
            const int col0 = ct * 128 + warpN * 64;
#pragma unroll
            for (int mb = 0; mb < 4; mb++) {
#pragma unroll
                for (int pr = 0; pr < 2; pr++) {
                    const int grow = row0 + warpM * 64 + mb * 16 + pr * 8 + g;
                    float v[16];
                    float tmax = -INFINITY;
#pragma unroll
                    for (int nb = 0; nb < 8; nb++) {
                        v[2 * nb] = acc[mb][nb][2 * pr] * SCALE_LOG2;
                        v[2 * nb + 1] = acc[mb][nb][2 * pr + 1] * SCALE_LOG2;
                        tmax = fmaxf(tmax, fmaxf(v[2 * nb], v[2 * nb + 1]));
                    }
                    tmax = fmaxf(tmax, __shfl_xor_sync(0xffffffffu, tmax, 1));
                    tmax = fmaxf(tmax, __shfl_xor_sync(0xffffffffu, tmax, 2));
                    float sum = 0.0f;
#pragma unroll
                    for (int nb = 0; nb < 8; nb++) {
                        const int gc = col0 + nb * 8 + q * 2;
                        sum += ex2f(v[2 * nb] - tmax) + ex2f(v[2 * nb + 1] - tmax);
                        if (gc == grow) g_pos[grow] = v[2 * nb];
                        if (gc + 1 == grow) g_pos[grow] = v[2 * nb + 1];
                    }
                    sum += __shfl_xor_sync(0xffffffffu, sum, 1);
                    sum += __shfl_xor_sync(0xffffffffu, sum, 2);
                    if (q == 0) {
                        g_m[sp][grow] = tmax;
                        g_l[sp][grow] = sum;
                    }
                }
            }
#pragma unroll
            for (int mb = 0; mb < 4; mb++)
#pragma unroll
                for (int nb = 0; nb < 8; nb++)
#pragma unroll
                    for (int c = 0; c < 4; c++) acc[mb][nb][c] = 0.0f;
        }
    }
}

// -------- fused combine + reduce (grid 32; last block finishes) --------
__global__ void cl_combine_kernel(float* __restrict__ out) {
    __shared__ float sh[256];
    const int i = blockIdx.x * 256 + threadIdx.x;
    float M = -INFINITY;
#pragma unroll 8
    for (int s = 0; s < NPART; s++) M = fmaxf(M, g_m[s][i]);
    float L = 0.0f;
#pragma unroll 8
    for (int s = 0; s < NPART; s++) L += g_l[s][i] * ex2f(g_m[s][i] - M);
    sh[threadIdx.x] = M + __log2f(L) - g_pos[i];
    __syncthreads();
    for (int o = 128; o > 0; o >>= 1) {
        if (threadIdx.x < o) sh[threadIdx.x] += sh[threadIdx.x + o];
        __syncthreads();
    }
    if (threadIdx.x == 0) {
        g_bsum[blockIdx.x] = sh[0];
        __threadfence();
        const unsigned int t = atomicAdd(&g_done, 1u);
        if (t == 31u) {
            float tot = 0.0f;
#pragma unroll
            for (int k = 0; k < 32; k++) tot += g_bsum[k];
            out[0] = tot * LN2;
            g_done = 0u;   // reset for graph replay
        }
    }
}

extern "C" void kernel_launch(void* const* d_in, const int* in_sizes, int n_in,
                              void* d_out, int out_size) {
    const float* X = (const float*)d_in[0];
    const float* Y = (const float*)d_in[1];
    float* out = (float*)d_out;

    cudaFuncSetAttribute(cl_mma_kernel, cudaFuncAttributeMaxDynamicSharedMemorySize, SMEM_TOTAL);

    cl_pre_kernel<<<4096, 256>>>(X, Y);
    cl_mma_kernel<<<NCTA, 128, SMEM_TOTAL>>>();
    cl_combine_kernel<<<32, 256>>>(out);
}